// round 10
// baseline (speedup 1.0000x reference)
#include <cuda_runtime.h>
#include <cuda_fp16.h>
#include <cstdint>
#include <cstddef>

// ---------------------------------------------------------------------------
// Problem constants
// ---------------------------------------------------------------------------
#define BATCH 4
#define SEQ   2048
#define DIM   1024

// GEMM tiling: 256x128 CTA tile, 8 warps of 64x64, K chunks of 64 fp16.
// Fatter M-tile cuts L2 operand traffic per FLOP to 0.75x (L2-BW-bound).
#define KC      64
#define LDT     72                      // padded row stride in fp16 (144 B)
#define TILE_A  (256 * LDT * 2)         // 36864 B  (A: 256 rows)
#define TILE_BB (128 * LDT * 2)         // 18432 B  (B: 128 rows)
#define STG_B   (TILE_A + TILE_BB)      // 55296 B per stage
#define NS      3                       // pipeline stages
#define SMEM_B  (NS * STG_B)            // 165888 B -> 1 CTA/SM
#define GT      256                     // threads per GEMM CTA (8 warps)

// ---------------------------------------------------------------------------
// PTX helpers (base sm_103 ISA: cp.async, ldmatrix, mma.sync)
// ---------------------------------------------------------------------------
__device__ __forceinline__ uint32_t smem_u32(const void* p) {
    uint32_t a;
    asm("{ .reg .u64 t; cvta.to.shared.u64 t, %1; cvt.u32.u64 %0, t; }"
        : "=r"(a) : "l"(p));
    return a;
}
__device__ __forceinline__ void cpa16(uint32_t dst, const void* src) {
    asm volatile("cp.async.cg.shared.global [%0], [%1], 16;"
                 :: "r"(dst), "l"(src));
}
__device__ __forceinline__ void cpa_commit() {
    asm volatile("cp.async.commit_group;");
}
__device__ __forceinline__ void ldm_x4(uint32_t* r, uint32_t addr) {
    asm volatile("ldmatrix.sync.aligned.m8n8.x4.shared.b16 {%0,%1,%2,%3}, [%4];"
                 : "=r"(r[0]), "=r"(r[1]), "=r"(r[2]), "=r"(r[3]) : "r"(addr));
}
__device__ __forceinline__ void mma16816(float* d, const uint32_t* a,
                                         uint32_t b0, uint32_t b1) {
    asm volatile(
        "mma.sync.aligned.m16n8k16.row.col.f32.f16.f16.f32 "
        "{%0,%1,%2,%3}, {%4,%5,%6,%7}, {%8,%9}, {%0,%1,%2,%3};"
        : "+f"(d[0]), "+f"(d[1]), "+f"(d[2]), "+f"(d[3])
        : "r"(a[0]), "r"(a[1]), "r"(a[2]), "r"(a[3]), "r"(b0), "r"(b1));
}
__device__ __forceinline__ uint32_t pack2h(float a, float b) {
    __half ha = __float2half_rn(a), hb = __float2half_rn(b);
    return (uint32_t)__half_as_ushort(ha) | ((uint32_t)__half_as_ushort(hb) << 16);
}

// ---------------------------------------------------------------------------
// Device scratch
// ---------------------------------------------------------------------------
#define RXD ((size_t)BATCH * SEQ * DIM)
#define RSS ((size_t)BATCH * SEQ * SEQ)
__device__ __half g_xh[RXD];                             // x fp16
__device__ __half g_wqkvth[3 * DIM * DIM];               // W_{q|k|v}^T fp16
__device__ __half g_woth[DIM * DIM];                     // Wo^T fp16
__device__ __half g_qkh[(size_t)BATCH * SEQ * 2 * DIM];  // Q|K fp16 [8192][2048]
__device__ __half g_vth[RXD];                            // V^T fp16 [B][DV][SEQ]
__device__ float  g_S[RSS];
__device__ __half g_ph[RSS];                             // P fp16
__device__ __half g_aoh[RXD];                            // AO fp16

// ---------------------------------------------------------------------------
// Async tile loads -> padded smem (row stride LDT fp16)
// ---------------------------------------------------------------------------
__device__ __forceinline__ void loadA_async(uint32_t base,                 // 256 rows
                                            const __half* __restrict__ gp,
                                            int ld, int tid) {
    #pragma unroll
    for (int i = 0; i < 8; i++) {
        int idx = i * GT + tid;           // 0..2047
        int row = idx >> 3;
        int c16 = idx & 7;
        cpa16(base + row * (LDT * 2) + c16 * 16,
              gp + (size_t)row * ld + c16 * 8);
    }
}
__device__ __forceinline__ void loadB_async(uint32_t base,                 // 128 rows
                                            const __half* __restrict__ gp,
                                            int ld, int tid) {
    #pragma unroll
    for (int i = 0; i < 4; i++) {
        int idx = i * GT + tid;           // 0..1023
        int row = idx >> 3;
        int c16 = idx & 7;
        cpa16(base + row * (LDT * 2) + c16 * 16,
              gp + (size_t)row * ld + c16 * 8);
    }
}

// ---------------------------------------------------------------------------
// Single-pass fp16 GEMM: C[M,N] = A[M,K] @ B[N,K]^T (both K-major)
// CTA tile 256x128; 8 warps of 64x64 (warp_m = wid>>1, warp_n = wid&1).
// MODE: 0 = fp32 out, 1 = fp16 out,
//       3 = fused QKV (n<2048 -> Q|K fp16; n>=2048 -> V^T fp16)
// CAUSAL: 0 none, 1 compacted lower-triangle grid (256-row tiles),
//         2 K-limit at (tileR+1)*256 (long rows first)
// ---------------------------------------------------------------------------
template<int MODE, int CAUSAL>
__global__ __launch_bounds__(GT, 1)
void hm1(const __half* __restrict__ A, const __half* __restrict__ B,
         float* __restrict__ C32, __half* __restrict__ Chi,
         __half* __restrict__ Vth,
         int Nld, int ldA, int ldB, int Kdim,
         size_t sA, size_t sB, size_t sC)
{
    int tileR, tileC;
    if (CAUSAL == 1) {
        // rows of 256: row r has 2r+2 col-tiles of 128; prefix = r(r+1)
        const int t = blockIdx.x;
        int r = (int)((sqrtf(4.0f * t + 1.0f) - 1.0f) * 0.5f);
        while ((r + 1) * (r + 2) <= t) r++;
        while (r * (r + 1) > t) r--;
        tileR = r;
        tileC = t - r * (r + 1);
    } else if (CAUSAL == 2) {
        tileR = gridDim.y - 1 - blockIdx.y;   // long-K rows first
        tileC = blockIdx.x;
    } else {
        tileR = blockIdx.y;
        tileC = blockIdx.x;
    }

    const int row0 = tileR * 256;
    const int col0 = tileC * 128;
    const size_t zb = blockIdx.z;

    extern __shared__ char smem[];
    const uint32_t sb = smem_u32(smem);
    const int tid  = threadIdx.x;
    const int wid  = tid >> 5;
    const int lane = tid & 31;
    const int warp_m = wid >> 1;          // 0..3
    const int warp_n = wid & 1;           // 0..1
    const int gq = lane >> 2;
    const int tq = lane & 3;

    int kEnd = Kdim;
    if (CAUSAL == 2) {
        int lim = (tileR + 1) * 256;
        if (lim < kEnd) kEnd = lim;
    }
    const int nChunks = kEnd / KC;

    const __half* pA = A + zb * sA + (size_t)row0 * ldA;
    const __half* pB = B + zb * sB + (size_t)col0 * ldB;

    const int a_r  = lane & 15;
    const int a_kq = (lane >> 4) << 3;
    const int b_r  = (lane & 7) + ((lane >= 16) ? 8 : 0);
    const int b_kq = ((lane >> 3) & 1) << 3;

    const uint32_t aoff0 = (warp_m * 64 + a_r) * (LDT * 2) + a_kq * 2;
    const uint32_t boff0 = (warp_n * 64 + b_r) * (LDT * 2) + b_kq * 2;

    float acc[4][8][4];
    #pragma unroll
    for (int i = 0; i < 4; i++)
        #pragma unroll
        for (int j = 0; j < 8; j++)
            #pragma unroll
            for (int q = 0; q < 4; q++) acc[i][j][q] = 0.0f;

    // prologue: prefetch NS-1 chunks (always commit so wait counts line up)
    #pragma unroll
    for (int s = 0; s < NS - 1; s++) {
        if (s < nChunks) {
            const uint32_t st = sb + s * STG_B;
            const int k0 = s * KC;
            loadA_async(st,          pA + k0, ldA, tid);
            loadB_async(st + TILE_A, pB + k0, ldB, tid);
        }
        cpa_commit();
    }

    for (int c = 0; c < nChunks; c++) {
        asm volatile("cp.async.wait_group %0;" :: "n"(NS - 2));
        __syncthreads();

        const uint32_t st = sb + (c % NS) * STG_B;
        #pragma unroll
        for (int ks = 0; ks < 4; ks++) {
            const uint32_t kb = ks * 32;      // 16 fp16 = 32 bytes
            uint32_t ah[4][4], bh[4][4];
            #pragma unroll
            for (int mb = 0; mb < 4; mb++)
                ldm_x4(ah[mb], st + aoff0 + mb * 16 * (LDT * 2) + kb);
            #pragma unroll
            for (int nh = 0; nh < 4; nh++)
                ldm_x4(bh[nh], st + TILE_A + boff0 + nh * 16 * (LDT * 2) + kb);
            #pragma unroll
            for (int mb = 0; mb < 4; mb++) {
                #pragma unroll
                for (int nb = 0; nb < 8; nb++) {
                    const int nh = nb >> 1, p = (nb & 1) * 2;
                    mma16816(acc[mb][nb], ah[mb], bh[nh][p], bh[nh][p + 1]);
                }
            }
        }

        // prefetch chunk c + NS - 1 into the stage just freed (no barrier
        // needed: that stage was last read in chunk c-1, and all warps
        // passed this chunk's top-of-loop barrier).
        const int cn = c + NS - 1;
        if (cn < nChunks) {
            const uint32_t stn = sb + (cn % NS) * STG_B;
            const int k0 = cn * KC;
            loadA_async(stn,          pA + k0, ldA, tid);
            loadB_async(stn + TILE_A, pB + k0, ldB, tid);
        }
        cpa_commit();
    }

    // ---------------- Epilogue ----------------
    const bool vregion = (MODE == 3) && (col0 >= 2048);
    if (!vregion) {
        #pragma unroll
        for (int mb = 0; mb < 4; mb++) {
            const int m = row0 + warp_m * 64 + mb * 16 + gq;
            #pragma unroll
            for (int nb = 0; nb < 8; nb++) {
                const int n = col0 + warp_n * 64 + nb * 8 + tq * 2;
                const float* cc = acc[mb][nb];
                if (MODE == 0) {
                    float* d0 = C32 + zb * sC + (size_t)m * Nld + n;
                    float* d1 = C32 + zb * sC + (size_t)(m + 8) * Nld + n;
                    *reinterpret_cast<float2*>(d0) = make_float2(cc[0], cc[1]);
                    *reinterpret_cast<float2*>(d1) = make_float2(cc[2], cc[3]);
                } else {
                    size_t o0 = zb * sC + (size_t)m * Nld + n;
                    size_t o1 = zb * sC + (size_t)(m + 8) * Nld + n;
                    *reinterpret_cast<uint32_t*>(Chi + o0) = pack2h(cc[0], cc[1]);
                    *reinterpret_cast<uint32_t*>(Chi + o1) = pack2h(cc[2], cc[3]);
                }
            }
        }
    } else {
        // V^T region: transpose 256(s) x 128(dv) through smem, write fp16
        float* smt = reinterpret_cast<float*>(smem);   // [256][129] = 132KB
        __syncthreads();
        #pragma unroll
        for (int mb = 0; mb < 4; mb++) {
            const int m = warp_m * 64 + mb * 16 + gq;
            #pragma unroll
            for (int nb = 0; nb < 8; nb++) {
                const int n = warp_n * 64 + nb * 8 + tq * 2;
                const float* cc = acc[mb][nb];
                smt[m * 129 + n]           = cc[0];
                smt[m * 129 + n + 1]       = cc[1];
                smt[(m + 8) * 129 + n]     = cc[2];
                smt[(m + 8) * 129 + n + 1] = cc[3];
            }
        }
        __syncthreads();
        const int b  = row0 >> 11;
        const int s0 = row0 & (SEQ - 1);
        const int nl = tid & 127;            // dv within tile
        const int sh = (tid >> 7) * 128;     // s half (0 or 128)
        const size_t base = (size_t)b * DIM * SEQ +
                            (size_t)(col0 - 2048 + nl) * SEQ + s0 + sh;
        #pragma unroll
        for (int u = 0; u < 128; u += 2) {
            *reinterpret_cast<uint32_t*>(Vth + base + u) =
                pack2h(smt[(sh + u) * 129 + nl], smt[(sh + u + 1) * 129 + nl]);
        }
    }
}

// ---------------------------------------------------------------------------
// Preprocess: x fp32 -> fp16
// ---------------------------------------------------------------------------
__global__ void split_x(const float* __restrict__ in,
                        __half* __restrict__ xh, size_t n4)
{
    size_t i = (size_t)blockIdx.x * blockDim.x + threadIdx.x;
    if (i >= n4) return;
    float4 v = reinterpret_cast<const float4*>(in)[i];
    uint2 o;
    o.x = pack2h(v.x, v.y);
    o.y = pack2h(v.z, v.w);
    reinterpret_cast<uint2*>(xh)[i] = o;
}

// W [K][N] fp32 -> W^T fp16; z selects Wq/Wk/Wv (into concat) or Wo.
__global__ void transpose_qkvo(const float* __restrict__ Wq,
                               const float* __restrict__ Wk,
                               const float* __restrict__ Wv,
                               const float* __restrict__ Wo,
                               __half* __restrict__ qkvh,
                               __half* __restrict__ woh)
{
    __shared__ float t[32][33];
    const int z = blockIdx.z;
    const float* in = (z == 0) ? Wq : (z == 1) ? Wk : (z == 2) ? Wv : Wo;
    __half* dh = (z < 3) ? qkvh + (size_t)z * DIM * DIM : woh;

    const int bx = blockIdx.x * 32, by = blockIdx.y * 32;
    const int x = threadIdx.x, y = threadIdx.y;   // 32 x 8
    #pragma unroll
    for (int i = 0; i < 32; i += 8)
        t[y + i][x] = in[(size_t)(by + y + i) * DIM + bx + x];
    __syncthreads();
    #pragma unroll
    for (int i = 0; i < 32; i += 8)
        dh[(size_t)(bx + y + i) * DIM + by + x] = __float2half_rn(t[x][y + i]);
}

// ---------------------------------------------------------------------------
// Causal softmax: fp32 S (lower triangle) -> fp16 P; zeros up to the next
// 256 boundary (PV reads K in 256-row-tile granularity now).
// ---------------------------------------------------------------------------
__global__ void softmax_causal(const float* __restrict__ Sbuf,
                               __half* __restrict__ Ph)
{
    const int i = blockIdx.x;
    const int b = blockIdx.y;
    const size_t off = ((size_t)b * SEQ + i) * SEQ;
    const float* row = Sbuf + off;
    const int n = i + 1;
    const float scale = 0.03125f;   // 1/sqrt(1024)

    __shared__ float red[256];
    const int tid = threadIdx.x;

    float m = -3.402823466e+38f;
    for (int j = tid; j < n; j += 256) m = fmaxf(m, row[j]);
    red[tid] = m;
    __syncthreads();
    #pragma unroll
    for (int s = 128; s > 0; s >>= 1) {
        if (tid < s) red[tid] = fmaxf(red[tid], red[tid + s]);
        __syncthreads();
    }
    const float mx = red[0] * scale;
    __syncthreads();

    float sum = 0.0f;
    for (int j = tid; j < n; j += 256) sum += __expf(row[j] * scale - mx);
    red[tid] = sum;
    __syncthreads();
    #pragma unroll
    for (int s = 128; s > 0; s >>= 1) {
        if (tid < s) red[tid] += red[tid + s];
        __syncthreads();
    }
    const float inv = 1.0f / red[0];

    for (int j = tid; j < n; j += 256)
        Ph[off + j] = __float2half_rn(__expf(row[j] * scale - mx) * inv);

    // zero the rest of the 256-aligned diagonal tile (PV K-limit granularity)
    const int tileEnd = ((i >> 8) + 1) << 8;
    for (int j = n + tid; j < tileEnd; j += 256)
        Ph[off + j] = __ushort_as_half((unsigned short)0);
}

// ---------------------------------------------------------------------------
// Launch
// ---------------------------------------------------------------------------
extern "C" void kernel_launch(void* const* d_in, const int* in_sizes, int n_in,
                              void* d_out, int out_size)
{
    const float* x  = (const float*)d_in[0];
    const float* Wq = (const float*)d_in[1];
    const float* Wk = (const float*)d_in[2];
    const float* Wv = (const float*)d_in[3];
    const float* Wo = (const float*)d_in[4];
    float* out = (float*)d_out;

    cudaFuncSetAttribute(hm1<3,0>, cudaFuncAttributeMaxDynamicSharedMemorySize, SMEM_B);
    cudaFuncSetAttribute(hm1<0,1>, cudaFuncAttributeMaxDynamicSharedMemorySize, SMEM_B);
    cudaFuncSetAttribute(hm1<1,2>, cudaFuncAttributeMaxDynamicSharedMemorySize, SMEM_B);
    cudaFuncSetAttribute(hm1<0,0>, cudaFuncAttributeMaxDynamicSharedMemorySize, SMEM_B);

    __half *xh, *qkvh, *woh, *qkh, *vth, *ph, *aoh;
    float* S;
    cudaGetSymbolAddress((void**)&xh, g_xh);
    cudaGetSymbolAddress((void**)&qkvh, g_wqkvth);
    cudaGetSymbolAddress((void**)&woh, g_woth);
    cudaGetSymbolAddress((void**)&qkh, g_qkh);
    cudaGetSymbolAddress((void**)&vth, g_vth);
    cudaGetSymbolAddress((void**)&ph, g_ph);
    cudaGetSymbolAddress((void**)&aoh, g_aoh);
    cudaGetSymbolAddress((void**)&S, g_S);

    const size_t sQK = (size_t)SEQ * 2 * DIM;   // per-batch Q|K row block
    const size_t sV  = (size_t)DIM * SEQ;
    const size_t sS  = (size_t)SEQ * SEQ;

    // 1) x -> fp16
    split_x<<<(unsigned)((RXD / 4 + 255) / 256), 256>>>(x, xh, RXD / 4);

    // 2) weights: transpose to fp16 (Wq|Wk|Wv concat, Wo separate)
    transpose_qkvo<<<dim3(DIM / 32, DIM / 32, 4), dim3(32, 8)>>>(
        Wq, Wk, Wv, Wo, qkvh, woh);

    // 3) fused QKV projection: [8192,1024] @ [1024,3072]
    //    n<2048: Q|K fp16; n>=2048: V^T fp16
    hm1<3,0><<<dim3(3 * DIM / 128, BATCH * SEQ / 256, 1), GT, SMEM_B>>>(
        xh, qkvh, nullptr, qkh, vth,
        2 * DIM, DIM, DIM, DIM, 0, 0, 0);

    // 4) scores = Q @ K^T per batch (compacted lower-triangle, 256-row tiles:
    //    72 tiles per batch)
    hm1<0,1><<<dim3(72, 1, BATCH), GT, SMEM_B>>>(
        qkh, qkh + DIM, S, nullptr, nullptr,
        SEQ, 2 * DIM, 2 * DIM, DIM, sQK, sQK, sS);

    // 5) softmax -> P fp16
    softmax_causal<<<dim3(SEQ, BATCH), 256>>>(S, ph);

    // 6) AO = P @ V (B = V^T, K-limited at 256 granularity, long rows first)
    hm1<1,2><<<dim3(DIM / 128, SEQ / 256, BATCH), GT, SMEM_B>>>(
        ph, vth, nullptr, aoh, nullptr,
        DIM, SEQ, SEQ, SEQ, sS, sV, (size_t)SEQ * DIM);

    // 7) out = AO @ Wo
    hm1<0,0><<<dim3(DIM / 128, BATCH * SEQ / 256, 1), GT, SMEM_B>>>(
        aoh, woh, out, nullptr, nullptr,
        DIM, DIM, DIM, DIM, 0, 0, 0);
}

// round 11
// speedup vs baseline: 1.0993x; 1.0993x over previous
#include <cuda_runtime.h>
#include <cuda_fp16.h>
#include <cstdint>
#include <cstddef>

// ---------------------------------------------------------------------------
// Problem constants
// ---------------------------------------------------------------------------
#define BATCH 4
#define SEQ   2048
#define DIM   1024

// GEMM tiling: 128x128 CTA tile, 4 warps of 64x64, K chunks of 64 fp16 (R9).
#define KC     64
#define LDT    72                       // padded row stride in fp16 (144 B)
#define TILE_P (128 * LDT * 2)          // 18432 B per tile
#define NTILES 2                        // A, B
#define STG_B  (NTILES * TILE_P)        // 36864 B
#define NS     3                        // pipeline stages
#define SMEM_B (NS * STG_B)             // 110592 B -> 2 CTAs/SM
#define GT     128                      // threads per GEMM CTA (4 warps)

#define SM_SCALE 0.03125f               // 1/sqrt(1024)

// ---------------------------------------------------------------------------
// PTX helpers (base sm_103 ISA: cp.async, ldmatrix, mma.sync)
// ---------------------------------------------------------------------------
__device__ __forceinline__ uint32_t smem_u32(const void* p) {
    uint32_t a;
    asm("{ .reg .u64 t; cvta.to.shared.u64 t, %1; cvt.u32.u64 %0, t; }"
        : "=r"(a) : "l"(p));
    return a;
}
__device__ __forceinline__ void cpa16(uint32_t dst, const void* src) {
    asm volatile("cp.async.cg.shared.global [%0], [%1], 16;"
                 :: "r"(dst), "l"(src));
}
__device__ __forceinline__ void cpa_commit() {
    asm volatile("cp.async.commit_group;");
}
__device__ __forceinline__ void ldm_x4(uint32_t* r, uint32_t addr) {
    asm volatile("ldmatrix.sync.aligned.m8n8.x4.shared.b16 {%0,%1,%2,%3}, [%4];"
                 : "=r"(r[0]), "=r"(r[1]), "=r"(r[2]), "=r"(r[3]) : "r"(addr));
}
__device__ __forceinline__ void mma16816(float* d, const uint32_t* a,
                                         uint32_t b0, uint32_t b1) {
    asm volatile(
        "mma.sync.aligned.m16n8k16.row.col.f32.f16.f16.f32 "
        "{%0,%1,%2,%3}, {%4,%5,%6,%7}, {%8,%9}, {%0,%1,%2,%3};"
        : "+f"(d[0]), "+f"(d[1]), "+f"(d[2]), "+f"(d[3])
        : "r"(a[0]), "r"(a[1]), "r"(a[2]), "r"(a[3]), "r"(b0), "r"(b1));
}
__device__ __forceinline__ uint32_t pack2h(float a, float b) {
    __half ha = __float2half_rn(a), hb = __float2half_rn(b);
    return (uint32_t)__half_as_ushort(ha) | ((uint32_t)__half_as_ushort(hb) << 16);
}

// ---------------------------------------------------------------------------
// Device scratch
// ---------------------------------------------------------------------------
#define RXD ((size_t)BATCH * SEQ * DIM)
#define RSS ((size_t)BATCH * SEQ * SEQ)
__device__ __half g_xh[RXD];                             // x fp16
__device__ __half g_wqkvth[3 * DIM * DIM];               // W_{q|k|v}^T fp16
__device__ __half g_woth[DIM * DIM];                     // Wo^T fp16
__device__ __half g_qkh[(size_t)BATCH * SEQ * 2 * DIM];  // Q|K fp16 [8192][2048]
__device__ __half g_vth[RXD];                            // V^T fp16 [B][DV][SEQ]
__device__ __half g_ph[RSS];                             // P = exp(s*scale) fp16
__device__ float  g_rsum[(size_t)BATCH * SEQ];           // row sums of P
__device__ __half g_aoh[RXD];                            // AO fp16 (normalized)

// ---------------------------------------------------------------------------
// Async tile load: 128 rows x 64 fp16 (K-major) -> padded smem (stride LDT)
// ---------------------------------------------------------------------------
__device__ __forceinline__ void load_tile_async(uint32_t base,
                                                const __half* __restrict__ gp,
                                                int ld, int tid) {
    #pragma unroll
    for (int i = 0; i < 8; i++) {
        int idx = i * GT + tid;           // 0..1023
        int row = idx >> 3;
        int c16 = idx & 7;
        cpa16(base + row * (LDT * 2) + c16 * 16,
              gp + (size_t)row * ld + c16 * 8);
    }
}

// ---------------------------------------------------------------------------
// Single-pass fp16 GEMM: C[M,N] = A[M,K] @ B[N,K]^T (both K-major)
// 4 warps of 64x64, explicit k-step operand double buffering, one barrier
// per chunk (NS=3 makes the post-compute barrier redundant).
// MODE: 0 = fp32 out (Wo)
//       1 = fp16 out normalized by rsum[row]  (PV; Rsum = read ptr)
//       2 = P = exp(scale*s) masked, fp16 out + rsum atomics (scores)
//       3 = fused QKV (n<2048 -> Q|K fp16; n>=2048 -> V^T fp16)
// CAUSAL: 0 none, 1 compacted lower-triangle grid, 2 K-limit (long rows first)
// ---------------------------------------------------------------------------
template<int MODE, int CAUSAL>
__global__ __launch_bounds__(GT, 2)
void hm1(const __half* __restrict__ A, const __half* __restrict__ B,
         float* __restrict__ Rsum, __half* __restrict__ Chi,
         __half* __restrict__ Vth, float* __restrict__ C32,
         int Nld, int ldA, int ldB, int Kdim,
         size_t sA, size_t sB, size_t sC)
{
    int tileR, tileC;
    if (CAUSAL == 1) {
        const int t = blockIdx.x;
        int r = (int)((sqrtf(8.0f * t + 1.0f) - 1.0f) * 0.5f);
        while ((r + 1) * (r + 2) / 2 <= t) r++;
        while (r * (r + 1) / 2 > t) r--;
        tileR = r;
        tileC = t - r * (r + 1) / 2;
    } else if (CAUSAL == 2) {
        tileR = gridDim.y - 1 - blockIdx.y;   // long-K rows first
        tileC = blockIdx.x;
    } else {
        tileR = blockIdx.y;
        tileC = blockIdx.x;
    }

    const int row0 = tileR * 128;
    const int col0 = tileC * 128;
    const size_t zb = blockIdx.z;

    extern __shared__ char smem[];
    const uint32_t sb = smem_u32(smem);
    const int tid  = threadIdx.x;
    const int wid  = tid >> 5;
    const int lane = tid & 31;
    const int warp_m = wid >> 1;          // 0..1
    const int warp_n = wid & 1;           // 0..1
    const int gq = lane >> 2;
    const int tq = lane & 3;

    int kEnd = Kdim;
    if (CAUSAL == 2) {
        int lim = (tileR + 1) * 128;
        if (lim < kEnd) kEnd = lim;
    }
    const int nChunks = kEnd / KC;

    const __half* pA = A + zb * sA + (size_t)row0 * ldA;
    const __half* pB = B + zb * sB + (size_t)col0 * ldB;

    const int a_r  = lane & 15;
    const int a_kq = (lane >> 4) << 3;
    const int b_r  = (lane & 7) + ((lane >= 16) ? 8 : 0);
    const int b_kq = ((lane >> 3) & 1) << 3;

    const uint32_t aoff0 = (warp_m * 64 + a_r) * (LDT * 2) + a_kq * 2;
    const uint32_t boff0 = (warp_n * 64 + b_r) * (LDT * 2) + b_kq * 2;

    float acc[4][8][4];
    #pragma unroll
    for (int i = 0; i < 4; i++)
        #pragma unroll
        for (int j = 0; j < 8; j++)
            #pragma unroll
            for (int q = 0; q < 4; q++) acc[i][j][q] = 0.0f;

    // prologue: prefetch NS-1 chunks (always commit so wait counts line up)
    #pragma unroll
    for (int s = 0; s < NS - 1; s++) {
        if (s < nChunks) {
            const uint32_t st = sb + s * STG_B;
            const int k0 = s * KC;
            load_tile_async(st,          pA + k0, ldA, tid);
            load_tile_async(st + TILE_P, pB + k0, ldB, tid);
        }
        cpa_commit();
    }

    uint32_t ah[2][4][4], bh[2][4][4];    // double-buffered k-step operands

    for (int c = 0; c < nChunks; c++) {
        asm volatile("cp.async.wait_group %0;" :: "n"(NS - 2));
        __syncthreads();

        const uint32_t st = sb + (c % NS) * STG_B;

        #pragma unroll
        for (int mb = 0; mb < 4; mb++)
            ldm_x4(ah[0][mb], st + aoff0 + mb * 16 * (LDT * 2));
        #pragma unroll
        for (int nh = 0; nh < 4; nh++)
            ldm_x4(bh[0][nh], st + TILE_P + boff0 + nh * 16 * (LDT * 2));

        #pragma unroll
        for (int ks = 0; ks < 4; ks++) {
            const int cur = ks & 1;
            if (ks < 3) {
                const uint32_t kb = (ks + 1) * 32;
                #pragma unroll
                for (int mb = 0; mb < 4; mb++)
                    ldm_x4(ah[cur ^ 1][mb],
                           st + aoff0 + mb * 16 * (LDT * 2) + kb);
                #pragma unroll
                for (int nh = 0; nh < 4; nh++)
                    ldm_x4(bh[cur ^ 1][nh],
                           st + TILE_P + boff0 + nh * 16 * (LDT * 2) + kb);
            }
            #pragma unroll
            for (int mb = 0; mb < 4; mb++) {
                #pragma unroll
                for (int nb = 0; nb < 8; nb++) {
                    const int nh = nb >> 1, p = (nb & 1) * 2;
                    mma16816(acc[mb][nb], ah[cur][mb],
                             bh[cur][nh][p], bh[cur][nh][p + 1]);
                }
            }
        }

        const int cn = c + NS - 1;
        if (cn < nChunks) {
            const uint32_t stn = sb + (cn % NS) * STG_B;
            const int k0 = cn * KC;
            load_tile_async(stn,          pA + k0, ldA, tid);
            load_tile_async(stn + TILE_P, pB + k0, ldB, tid);
        }
        cpa_commit();
    }

    // ---------------- Epilogue ----------------
    if (MODE == 2) {
        // scores -> P = exp(scale*s) (masked), fp16; accumulate row sums
        #pragma unroll
        for (int mb = 0; mb < 4; mb++) {
            const int m0 = row0 + warp_m * 64 + mb * 16 + gq;   // local row
            const int m1 = m0 + 8;
            float sum0 = 0.0f, sum1 = 0.0f;
            #pragma unroll
            for (int nb = 0; nb < 8; nb++) {
                const int n = col0 + warp_n * 64 + nb * 8 + tq * 2;
                const float* cc = acc[mb][nb];
                float p00 = (n     <= m0) ? __expf(cc[0] * SM_SCALE) : 0.0f;
                float p01 = (n + 1 <= m0) ? __expf(cc[1] * SM_SCALE) : 0.0f;
                float p10 = (n     <= m1) ? __expf(cc[2] * SM_SCALE) : 0.0f;
                float p11 = (n + 1 <= m1) ? __expf(cc[3] * SM_SCALE) : 0.0f;
                sum0 += p00 + p01;
                sum1 += p10 + p11;
                size_t o0 = zb * sC + (size_t)m0 * Nld + n;
                size_t o1 = zb * sC + (size_t)m1 * Nld + n;
                *reinterpret_cast<uint32_t*>(Chi + o0) = pack2h(p00, p01);
                *reinterpret_cast<uint32_t*>(Chi + o1) = pack2h(p10, p11);
            }
            // reduce across the 4 tq lanes sharing each row
            #pragma unroll
            for (int o = 1; o < 4; o <<= 1) {
                sum0 += __shfl_xor_sync(0xffffffffu, sum0, o);
                sum1 += __shfl_xor_sync(0xffffffffu, sum1, o);
            }
            if (tq == 0) {
                atomicAdd(&Rsum[zb * SEQ + m0], sum0);
                atomicAdd(&Rsum[zb * SEQ + m1], sum1);
            }
        }
    } else if (MODE != 3 || col0 < 2048) {
        #pragma unroll
        for (int mb = 0; mb < 4; mb++) {
            const int m = row0 + warp_m * 64 + mb * 16 + gq;
            float inv0 = 1.0f, inv1 = 1.0f;
            if (MODE == 1) {
                inv0 = 1.0f / Rsum[zb * SEQ + m];
                inv1 = 1.0f / Rsum[zb * SEQ + m + 8];
            }
            #pragma unroll
            for (int nb = 0; nb < 8; nb++) {
                const int n = col0 + warp_n * 64 + nb * 8 + tq * 2;
                const float* cc = acc[mb][nb];
                if (MODE == 0) {
                    float* d0 = C32 + zb * sC + (size_t)m * Nld + n;
                    float* d1 = C32 + zb * sC + (size_t)(m + 8) * Nld + n;
                    *reinterpret_cast<float2*>(d0) = make_float2(cc[0], cc[1]);
                    *reinterpret_cast<float2*>(d1) = make_float2(cc[2], cc[3]);
                } else {
                    size_t o0 = zb * sC + (size_t)m * Nld + n;
                    size_t o1 = zb * sC + (size_t)(m + 8) * Nld + n;
                    *reinterpret_cast<uint32_t*>(Chi + o0) =
                        pack2h(cc[0] * inv0, cc[1] * inv0);
                    *reinterpret_cast<uint32_t*>(Chi + o1) =
                        pack2h(cc[2] * inv1, cc[3] * inv1);
                }
            }
        }
    } else {
        // V^T region: transpose through smem, write fp16
        float* smt = reinterpret_cast<float*>(smem);   // [128][129]
        __syncthreads();
        #pragma unroll
        for (int mb = 0; mb < 4; mb++) {
            const int m = warp_m * 64 + mb * 16 + gq;
            #pragma unroll
            for (int nb = 0; nb < 8; nb++) {
                const int n = warp_n * 64 + nb * 8 + tq * 2;
                const float* cc = acc[mb][nb];
                smt[m * 129 + n]           = cc[0];
                smt[m * 129 + n + 1]       = cc[1];
                smt[(m + 8) * 129 + n]     = cc[2];
                smt[(m + 8) * 129 + n + 1] = cc[3];
            }
        }
        __syncthreads();
        const int b  = row0 >> 11;
        const int s0 = row0 & (SEQ - 1);
        const int nl = tid;                 // 0..127 (dv within tile)
        const size_t base = (size_t)b * DIM * SEQ +
                            (size_t)(col0 - 2048 + nl) * SEQ + s0;
        #pragma unroll
        for (int u = 0; u < 128; u += 2) {
            *reinterpret_cast<uint32_t*>(Vth + base + u) =
                pack2h(smt[u * 129 + nl], smt[(u + 1) * 129 + nl]);
        }
    }
}

// ---------------------------------------------------------------------------
// Preprocess: x fp32 -> fp16; also zeroes the rsum accumulator
// ---------------------------------------------------------------------------
__global__ void split_x(const float* __restrict__ in,
                        __half* __restrict__ xh,
                        float* __restrict__ rsum, size_t n4)
{
    size_t i = (size_t)blockIdx.x * blockDim.x + threadIdx.x;
    if (i >= n4) return;
    if (i < (size_t)BATCH * SEQ) rsum[i] = 0.0f;
    float4 v = reinterpret_cast<const float4*>(in)[i];
    uint2 o;
    o.x = pack2h(v.x, v.y);
    o.y = pack2h(v.z, v.w);
    reinterpret_cast<uint2*>(xh)[i] = o;
}

// W [K][N] fp32 -> W^T fp16; z selects Wq/Wk/Wv (into concat) or Wo.
__global__ void transpose_qkvo(const float* __restrict__ Wq,
                               const float* __restrict__ Wk,
                               const float* __restrict__ Wv,
                               const float* __restrict__ Wo,
                               __half* __restrict__ qkvh,
                               __half* __restrict__ woh)
{
    __shared__ float t[32][33];
    const int z = blockIdx.z;
    const float* in = (z == 0) ? Wq : (z == 1) ? Wk : (z == 2) ? Wv : Wo;
    __half* dh = (z < 3) ? qkvh + (size_t)z * DIM * DIM : woh;

    const int bx = blockIdx.x * 32, by = blockIdx.y * 32;
    const int x = threadIdx.x, y = threadIdx.y;   // 32 x 8
    #pragma unroll
    for (int i = 0; i < 32; i += 8)
        t[y + i][x] = in[(size_t)(by + y + i) * DIM + bx + x];
    __syncthreads();
    #pragma unroll
    for (int i = 0; i < 32; i += 8)
        dh[(size_t)(bx + y + i) * DIM + by + x] = __float2half_rn(t[x][y + i]);
}

// ---------------------------------------------------------------------------
// Launch
// ---------------------------------------------------------------------------
extern "C" void kernel_launch(void* const* d_in, const int* in_sizes, int n_in,
                              void* d_out, int out_size)
{
    const float* x  = (const float*)d_in[0];
    const float* Wq = (const float*)d_in[1];
    const float* Wk = (const float*)d_in[2];
    const float* Wv = (const float*)d_in[3];
    const float* Wo = (const float*)d_in[4];
    float* out = (float*)d_out;

    cudaFuncSetAttribute(hm1<3,0>, cudaFuncAttributeMaxDynamicSharedMemorySize, SMEM_B);
    cudaFuncSetAttribute(hm1<2,1>, cudaFuncAttributeMaxDynamicSharedMemorySize, SMEM_B);
    cudaFuncSetAttribute(hm1<1,2>, cudaFuncAttributeMaxDynamicSharedMemorySize, SMEM_B);
    cudaFuncSetAttribute(hm1<0,0>, cudaFuncAttributeMaxDynamicSharedMemorySize, SMEM_B);

    __half *xh, *qkvh, *woh, *qkh, *vth, *ph, *aoh;
    float* rsum;
    cudaGetSymbolAddress((void**)&xh, g_xh);
    cudaGetSymbolAddress((void**)&qkvh, g_wqkvth);
    cudaGetSymbolAddress((void**)&woh, g_woth);
    cudaGetSymbolAddress((void**)&qkh, g_qkh);
    cudaGetSymbolAddress((void**)&vth, g_vth);
    cudaGetSymbolAddress((void**)&ph, g_ph);
    cudaGetSymbolAddress((void**)&aoh, g_aoh);
    cudaGetSymbolAddress((void**)&rsum, g_rsum);

    const size_t sQK = (size_t)SEQ * 2 * DIM;   // per-batch Q|K row block
    const size_t sV  = (size_t)DIM * SEQ;
    const size_t sS  = (size_t)SEQ * SEQ;

    // 1) x -> fp16 (+ rsum zeroing)
    split_x<<<(unsigned)((RXD / 4 + 255) / 256), 256>>>(x, xh, rsum, RXD / 4);

    // 2) weights: transpose to fp16 (Wq|Wk|Wv concat, Wo separate)
    transpose_qkvo<<<dim3(DIM / 32, DIM / 32, 4), dim3(32, 8)>>>(
        Wq, Wk, Wv, Wo, qkvh, woh);

    // 3) fused QKV projection: [8192,1024] @ [1024,3072]
    hm1<3,0><<<dim3(3 * DIM / 128, BATCH * SEQ / 128, 1), GT, SMEM_B>>>(
        xh, qkvh, nullptr, qkh, vth, nullptr,
        2 * DIM, DIM, DIM, DIM, 0, 0, 0);

    // 4) scores -> P = exp(scale * QK^T) fp16 + row sums (no softmax kernel!)
    hm1<2,1><<<dim3(136, 1, BATCH), GT, SMEM_B>>>(
        qkh, qkh + DIM, rsum, ph, nullptr, nullptr,
        SEQ, 2 * DIM, 2 * DIM, DIM, sQK, sQK, sS);

    // 5) AO = (P @ V) / rsum   (B = V^T, K-limited, long rows first)
    hm1<1,2><<<dim3(DIM / 128, SEQ / 128, BATCH), GT, SMEM_B>>>(
        ph, vth, rsum, aoh, nullptr, nullptr,
        DIM, SEQ, SEQ, SEQ, sS, sV, (size_t)SEQ * DIM);

    // 6) out = AO @ Wo
    hm1<0,0><<<dim3(DIM / 128, BATCH * SEQ / 128, 1), GT, SMEM_B>>>(
        aoh, woh, nullptr, nullptr, nullptr, out,
        DIM, DIM, DIM, DIM, 0, 0, 0);
}

// round 12
// speedup vs baseline: 1.2340x; 1.1225x over previous
#include <cuda_runtime.h>
#include <cuda_fp16.h>
#include <cstdint>
#include <cstddef>

// ---------------------------------------------------------------------------
// Problem constants
// ---------------------------------------------------------------------------
#define BATCH 4
#define SEQ   2048
#define DIM   1024

// GEMM tiling: 128x128 CTA tile, 4 warps of 64x64, K chunks of 64 fp16 (R9).
#define KC     64
#define LDT    72                       // padded row stride in fp16 (144 B)
#define TILE_P (128 * LDT * 2)          // 18432 B per tile
#define STG_B  (2 * TILE_P)             // 36864 B (A + B)
#define NS     3                        // pipeline stages
#define SMEM_B (NS * STG_B)             // 110592 B -> 2 CTAs/SM
#define GT     128                      // threads per CTA (4 warps)

#define SM_SCALE 0.03125f               // 1/sqrt(1024)

// Megakernel segment boundaries
#define N_QKV   1536                    // 24 x 64
#define N_SC    544                     // 136 tri-tiles x 4 batches
#define N_PV    512                     // 8 x 16 x 4
#define N_WO    512                     // 8 x 64
#define B_SC    (N_QKV)
#define B_PV    (N_QKV + N_SC)
#define B_WO    (N_QKV + N_SC + N_PV)
#define N_ALL   (N_QKV + N_SC + N_PV + N_WO)   // 3104

// ---------------------------------------------------------------------------
// PTX helpers (base sm_103 ISA: cp.async, ldmatrix, mma.sync)
// ---------------------------------------------------------------------------
__device__ __forceinline__ uint32_t smem_u32(const void* p) {
    uint32_t a;
    asm("{ .reg .u64 t; cvta.to.shared.u64 t, %1; cvt.u32.u64 %0, t; }"
        : "=r"(a) : "l"(p));
    return a;
}
__device__ __forceinline__ void cpa16(uint32_t dst, const void* src) {
    asm volatile("cp.async.cg.shared.global [%0], [%1], 16;"
                 :: "r"(dst), "l"(src));
}
__device__ __forceinline__ void cpa_commit() {
    asm volatile("cp.async.commit_group;");
}
__device__ __forceinline__ void ldm_x4(uint32_t* r, uint32_t addr) {
    asm volatile("ldmatrix.sync.aligned.m8n8.x4.shared.b16 {%0,%1,%2,%3}, [%4];"
                 : "=r"(r[0]), "=r"(r[1]), "=r"(r[2]), "=r"(r[3]) : "r"(addr));
}
__device__ __forceinline__ void mma16816(float* d, const uint32_t* a,
                                         uint32_t b0, uint32_t b1) {
    asm volatile(
        "mma.sync.aligned.m16n8k16.row.col.f32.f16.f16.f32 "
        "{%0,%1,%2,%3}, {%4,%5,%6,%7}, {%8,%9}, {%0,%1,%2,%3};"
        : "+f"(d[0]), "+f"(d[1]), "+f"(d[2]), "+f"(d[3])
        : "r"(a[0]), "r"(a[1]), "r"(a[2]), "r"(a[3]), "r"(b0), "r"(b1));
}
__device__ __forceinline__ uint32_t pack2h(float a, float b) {
    __half ha = __float2half_rn(a), hb = __float2half_rn(b);
    return (uint32_t)__half_as_ushort(ha) | ((uint32_t)__half_as_ushort(hb) << 16);
}

// ---------------------------------------------------------------------------
// Device scratch + dependency counters
// ---------------------------------------------------------------------------
#define RXD ((size_t)BATCH * SEQ * DIM)
#define RSS ((size_t)BATCH * SEQ * SEQ)
__device__ __half g_xh[RXD];                             // x fp16
__device__ __half g_wqkvth[3 * DIM * DIM];               // W_{q|k|v}^T fp16
__device__ __half g_woth[DIM * DIM];                     // Wo^T fp16
__device__ __half g_qkh[(size_t)BATCH * SEQ * 2 * DIM];  // Q|K fp16 [8192][2048]
__device__ __half g_vth[RXD];                            // V^T fp16 [B][DV][SEQ]
__device__ __half g_ph[RSS];                             // P = exp(s*scale) fp16
__device__ float  g_rsum[(size_t)BATCH * SEQ];           // row sums of P
__device__ __half g_aoh[RXD];                            // AO fp16 (normalized)
// counters: [0:64) qk rows done(16), [64:128) v rows done(8),
//           [128:192) scores rows done(r+1), [192:256) pv rows done(8)
__device__ int    g_cnt[256];

__device__ __forceinline__ void wait_cnt(int idx, int target) {
    volatile int* p = &g_cnt[idx];
    while (*p < target) __nanosleep(64);
}

// ---------------------------------------------------------------------------
// Async tile load: 128 rows x 64 fp16 (K-major) -> padded smem (stride LDT)
// ---------------------------------------------------------------------------
__device__ __forceinline__ void load_tile_async(uint32_t base,
                                                const __half* __restrict__ gp,
                                                int ld, int tid) {
    #pragma unroll
    for (int i = 0; i < 8; i++) {
        int idx = i * GT + tid;           // 0..1023
        int row = idx >> 3;
        int c16 = idx & 7;
        cpa16(base + row * (LDT * 2) + c16 * 16,
              gp + (size_t)row * ld + c16 * 8);
    }
}

// ---------------------------------------------------------------------------
// Megakernel: QKV -> scores(+exp) -> PV(/rsum) -> Wo in ONE launch.
// Dependencies enforced by g_cnt counters; producers always have smaller
// blockIdx than consumers (deadlock-free under in-order CTA dispatch).
// ---------------------------------------------------------------------------
__global__ __launch_bounds__(GT, 2)
void mega(float* __restrict__ out)
{
    const int bid = blockIdx.x;
    const int tid  = threadIdx.x;
    const int wid  = tid >> 5;
    const int lane = tid & 31;
    const int warp_m = wid >> 1;          // 0..1
    const int warp_n = wid & 1;           // 0..1
    const int gq = lane >> 2;
    const int tq = lane & 3;

    int mode, row0, col0, zb = 0, nChunks, pubIdx = -1;
    const __half* pA;
    const __half* pB;
    int ldA, ldB;

    if (bid < B_SC) {                                   // ---- QKV ----
        mode = 3;
        const int x = bid % 24, y = bid / 24;           // y = global M-block
        row0 = y * 128; col0 = x * 128;
        pA = g_xh + (size_t)row0 * DIM;
        pB = g_wqkvth + (size_t)col0 * DIM;
        ldA = DIM; ldB = DIM;
        nChunks = DIM / KC;
        pubIdx = (x < 16) ? y : 64 + y;
    } else if (bid < B_PV) {                            // ---- scores ----
        mode = 2;
        const int t = bid - B_SC;
        zb = t & 3;
        int tt = t >> 2;                                // 0..135, r descending
        int r = 15, acc = 0;
        while (tt >= acc + (r + 1)) { acc += r + 1; r--; }
        const int c = tt - acc;
        row0 = r * 128; col0 = c * 128;
        pA = g_qkh + (size_t)zb * (SEQ * 2 * DIM) + (size_t)row0 * (2 * DIM);
        pB = g_qkh + DIM + (size_t)zb * (SEQ * 2 * DIM) + (size_t)col0 * (2 * DIM);
        ldA = 2 * DIM; ldB = 2 * DIM;
        nChunks = DIM / KC;
        pubIdx = 128 + zb * 16 + r;
        if (tid == 0) {
            wait_cnt(zb * 16 + r, 16);
            wait_cnt(zb * 16 + c, 16);
            __threadfence();
        }
        __syncthreads();
    } else if (bid < B_WO) {                            // ---- PV ----
        mode = 1;
        const int t = bid - B_PV;
        zb = t & 3;
        const int u = t >> 2;
        const int r = 15 - (u >> 3);                    // long rows first
        const int x = u & 7;
        row0 = r * 128; col0 = x * 128;
        pA = g_ph + (size_t)zb * ((size_t)SEQ * SEQ) + (size_t)row0 * SEQ;
        pB = g_vth + (size_t)zb * ((size_t)DIM * SEQ) + (size_t)col0 * SEQ;
        ldA = SEQ; ldB = SEQ;
        nChunks = ((r + 1) * 128) / KC;
        pubIdx = 192 + zb * 16 + r;
        if (tid == 0) {
            for (int j = 0; j <= r; j++) wait_cnt(64 + zb * 16 + j, 8);
            wait_cnt(128 + zb * 16 + r, r + 1);
            __threadfence();
        }
        __syncthreads();
    } else {                                            // ---- Wo ----
        mode = 0;
        const int t = bid - B_WO;
        const int q = t >> 3;                           // 0..63
        const int x = t & 7;
        const int b = q & 3;
        const int r = 15 - (q >> 2);                    // match PV publish order
        const int m = b * 16 + r;
        row0 = m * 128; col0 = x * 128;
        pA = g_aoh + (size_t)row0 * DIM;
        pB = g_woth + (size_t)col0 * DIM;
        ldA = DIM; ldB = DIM;
        nChunks = DIM / KC;
        if (tid == 0) { wait_cnt(192 + m, 8); __threadfence(); }
        __syncthreads();
    }

    // ---------------- Shared mainloop (R11) ----------------
    extern __shared__ char smem[];
    const uint32_t sb = smem_u32(smem);

    const int a_r  = lane & 15;
    const int a_kq = (lane >> 4) << 3;
    const int b_r  = (lane & 7) + ((lane >= 16) ? 8 : 0);
    const int b_kq = ((lane >> 3) & 1) << 3;
    const uint32_t aoff0 = (warp_m * 64 + a_r) * (LDT * 2) + a_kq * 2;
    const uint32_t boff0 = (warp_n * 64 + b_r) * (LDT * 2) + b_kq * 2;

    float acc[4][8][4];
    #pragma unroll
    for (int i = 0; i < 4; i++)
        #pragma unroll
        for (int j = 0; j < 8; j++)
            #pragma unroll
            for (int q = 0; q < 4; q++) acc[i][j][q] = 0.0f;

    #pragma unroll
    for (int s = 0; s < NS - 1; s++) {
        if (s < nChunks) {
            const uint32_t st = sb + s * STG_B;
            const int k0 = s * KC;
            load_tile_async(st,          pA + k0, ldA, tid);
            load_tile_async(st + TILE_P, pB + k0, ldB, tid);
        }
        cpa_commit();
    }

    uint32_t ah[2][4][4], bh[2][4][4];

    for (int c = 0; c < nChunks; c++) {
        asm volatile("cp.async.wait_group %0;" :: "n"(NS - 2));
        __syncthreads();

        const uint32_t st = sb + (c % NS) * STG_B;

        #pragma unroll
        for (int mb = 0; mb < 4; mb++)
            ldm_x4(ah[0][mb], st + aoff0 + mb * 16 * (LDT * 2));
        #pragma unroll
        for (int nh = 0; nh < 4; nh++)
            ldm_x4(bh[0][nh], st + TILE_P + boff0 + nh * 16 * (LDT * 2));

        #pragma unroll
        for (int ks = 0; ks < 4; ks++) {
            const int cur = ks & 1;
            if (ks < 3) {
                const uint32_t kb = (ks + 1) * 32;
                #pragma unroll
                for (int mb = 0; mb < 4; mb++)
                    ldm_x4(ah[cur ^ 1][mb],
                           st + aoff0 + mb * 16 * (LDT * 2) + kb);
                #pragma unroll
                for (int nh = 0; nh < 4; nh++)
                    ldm_x4(bh[cur ^ 1][nh],
                           st + TILE_P + boff0 + nh * 16 * (LDT * 2) + kb);
            }
            #pragma unroll
            for (int mb = 0; mb < 4; mb++) {
                #pragma unroll
                for (int nb = 0; nb < 8; nb++) {
                    const int nh = nb >> 1, p = (nb & 1) * 2;
                    mma16816(acc[mb][nb], ah[cur][mb],
                             bh[cur][nh][p], bh[cur][nh][p + 1]);
                }
            }
        }

        const int cn = c + NS - 1;
        if (cn < nChunks) {
            const uint32_t stn = sb + (cn % NS) * STG_B;
            const int k0 = cn * KC;
            load_tile_async(stn,          pA + k0, ldA, tid);
            load_tile_async(stn + TILE_P, pB + k0, ldB, tid);
        }
        cpa_commit();
    }

    // ---------------- Epilogues ----------------
    if (mode == 2) {
        // scores -> P = exp(scale*s) masked, fp16 + row-sum atomics
        #pragma unroll
        for (int mb = 0; mb < 4; mb++) {
            const int m0 = row0 + warp_m * 64 + mb * 16 + gq;
            const int m1 = m0 + 8;
            float sum0 = 0.0f, sum1 = 0.0f;
            #pragma unroll
            for (int nb = 0; nb < 8; nb++) {
                const int n = col0 + warp_n * 64 + nb * 8 + tq * 2;
                const float* cc = acc[mb][nb];
                float p00 = (n     <= m0) ? __expf(cc[0] * SM_SCALE) : 0.0f;
                float p01 = (n + 1 <= m0) ? __expf(cc[1] * SM_SCALE) : 0.0f;
                float p10 = (n     <= m1) ? __expf(cc[2] * SM_SCALE) : 0.0f;
                float p11 = (n + 1 <= m1) ? __expf(cc[3] * SM_SCALE) : 0.0f;
                sum0 += p00 + p01;
                sum1 += p10 + p11;
                size_t o0 = (size_t)zb * SEQ * SEQ + (size_t)m0 * SEQ + n;
                size_t o1 = (size_t)zb * SEQ * SEQ + (size_t)m1 * SEQ + n;
                *reinterpret_cast<uint32_t*>(g_ph + o0) = pack2h(p00, p01);
                *reinterpret_cast<uint32_t*>(g_ph + o1) = pack2h(p10, p11);
            }
            #pragma unroll
            for (int o = 1; o < 4; o <<= 1) {
                sum0 += __shfl_xor_sync(0xffffffffu, sum0, o);
                sum1 += __shfl_xor_sync(0xffffffffu, sum1, o);
            }
            if (tq == 0) {
                atomicAdd(&g_rsum[(size_t)zb * SEQ + m0], sum0);
                atomicAdd(&g_rsum[(size_t)zb * SEQ + m1], sum1);
            }
        }
    } else if (mode == 1) {
        // PV -> AO = acc / rsum, fp16
        #pragma unroll
        for (int mb = 0; mb < 4; mb++) {
            const int m = row0 + warp_m * 64 + mb * 16 + gq;
            const float inv0 = 1.0f / g_rsum[(size_t)zb * SEQ + m];
            const float inv1 = 1.0f / g_rsum[(size_t)zb * SEQ + m + 8];
            #pragma unroll
            for (int nb = 0; nb < 8; nb++) {
                const int n = col0 + warp_n * 64 + nb * 8 + tq * 2;
                const float* cc = acc[mb][nb];
                size_t o0 = (size_t)zb * SEQ * DIM + (size_t)m * DIM + n;
                size_t o1 = (size_t)zb * SEQ * DIM + (size_t)(m + 8) * DIM + n;
                *reinterpret_cast<uint32_t*>(g_aoh + o0) =
                    pack2h(cc[0] * inv0, cc[1] * inv0);
                *reinterpret_cast<uint32_t*>(g_aoh + o1) =
                    pack2h(cc[2] * inv1, cc[3] * inv1);
            }
        }
    } else if (mode == 0) {
        // Wo -> out fp32
        #pragma unroll
        for (int mb = 0; mb < 4; mb++) {
            const int m = row0 + warp_m * 64 + mb * 16 + gq;
            #pragma unroll
            for (int nb = 0; nb < 8; nb++) {
                const int n = col0 + warp_n * 64 + nb * 8 + tq * 2;
                const float* cc = acc[mb][nb];
                float* d0 = out + (size_t)m * DIM + n;
                float* d1 = out + (size_t)(m + 8) * DIM + n;
                *reinterpret_cast<float2*>(d0) = make_float2(cc[0], cc[1]);
                *reinterpret_cast<float2*>(d1) = make_float2(cc[2], cc[3]);
            }
        }
    } else if (col0 < 2048) {
        // QKV, Q|K region -> fp16
        #pragma unroll
        for (int mb = 0; mb < 4; mb++) {
            const int m = row0 + warp_m * 64 + mb * 16 + gq;   // global row
            #pragma unroll
            for (int nb = 0; nb < 8; nb++) {
                const int n = col0 + warp_n * 64 + nb * 8 + tq * 2;
                const float* cc = acc[mb][nb];
                size_t o0 = (size_t)m * (2 * DIM) + n;
                size_t o1 = (size_t)(m + 8) * (2 * DIM) + n;
                *reinterpret_cast<uint32_t*>(g_qkh + o0) = pack2h(cc[0], cc[1]);
                *reinterpret_cast<uint32_t*>(g_qkh + o1) = pack2h(cc[2], cc[3]);
            }
        }
    } else {
        // QKV, V^T region: transpose through smem, write fp16
        float* smt = reinterpret_cast<float*>(smem);   // [128][129]
        __syncthreads();
        #pragma unroll
        for (int mb = 0; mb < 4; mb++) {
            const int m = warp_m * 64 + mb * 16 + gq;
            #pragma unroll
            for (int nb = 0; nb < 8; nb++) {
                const int n = warp_n * 64 + nb * 8 + tq * 2;
                const float* cc = acc[mb][nb];
                smt[m * 129 + n]           = cc[0];
                smt[m * 129 + n + 1]       = cc[1];
                smt[(m + 8) * 129 + n]     = cc[2];
                smt[(m + 8) * 129 + n + 1] = cc[3];
            }
        }
        __syncthreads();
        const int b  = row0 >> 11;
        const int s0 = row0 & (SEQ - 1);
        const int nl = tid;                 // 0..127 (dv within tile)
        const size_t base = (size_t)b * DIM * SEQ +
                            (size_t)(col0 - 2048 + nl) * SEQ + s0;
        #pragma unroll
        for (int u = 0; u < 128; u += 2) {
            *reinterpret_cast<uint32_t*>(g_vth + base + u) =
                pack2h(smt[u * 129 + nl], smt[(u + 1) * 129 + nl]);
        }
    }

    // ---------------- Publish completion ----------------
    __syncthreads();
    if (tid == 0 && pubIdx >= 0) {
        __threadfence();
        atomicAdd(&g_cnt[pubIdx], 1);
    }
}

// ---------------------------------------------------------------------------
// Preprocess: x fp32 -> fp16; zero rsum and dependency counters
// ---------------------------------------------------------------------------
__global__ void split_x(const float* __restrict__ in,
                        __half* __restrict__ xh,
                        float* __restrict__ rsum,
                        int* __restrict__ cnt, size_t n4)
{
    size_t i = (size_t)blockIdx.x * blockDim.x + threadIdx.x;
    if (i >= n4) return;
    if (i < (size_t)BATCH * SEQ) rsum[i] = 0.0f;
    if (i < 256) cnt[i] = 0;
    float4 v = reinterpret_cast<const float4*>(in)[i];
    uint2 o;
    o.x = pack2h(v.x, v.y);
    o.y = pack2h(v.z, v.w);
    reinterpret_cast<uint2*>(xh)[i] = o;
}

// W [K][N] fp32 -> W^T fp16; z selects Wq/Wk/Wv (into concat) or Wo.
__global__ void transpose_qkvo(const float* __restrict__ Wq,
                               const float* __restrict__ Wk,
                               const float* __restrict__ Wv,
                               const float* __restrict__ Wo,
                               __half* __restrict__ qkvh,
                               __half* __restrict__ woh)
{
    __shared__ float t[32][33];
    const int z = blockIdx.z;
    const float* in = (z == 0) ? Wq : (z == 1) ? Wk : (z == 2) ? Wv : Wo;
    __half* dh = (z < 3) ? qkvh + (size_t)z * DIM * DIM : woh;

    const int bx = blockIdx.x * 32, by = blockIdx.y * 32;
    const int x = threadIdx.x, y = threadIdx.y;   // 32 x 8
    #pragma unroll
    for (int i = 0; i < 32; i += 8)
        t[y + i][x] = in[(size_t)(by + y + i) * DIM + bx + x];
    __syncthreads();
    #pragma unroll
    for (int i = 0; i < 32; i += 8)
        dh[(size_t)(bx + y + i) * DIM + by + x] = __float2half_rn(t[x][y + i]);
}

// ---------------------------------------------------------------------------
// Launch
// ---------------------------------------------------------------------------
extern "C" void kernel_launch(void* const* d_in, const int* in_sizes, int n_in,
                              void* d_out, int out_size)
{
    const float* x  = (const float*)d_in[0];
    const float* Wq = (const float*)d_in[1];
    const float* Wk = (const float*)d_in[2];
    const float* Wv = (const float*)d_in[3];
    const float* Wo = (const float*)d_in[4];
    float* out = (float*)d_out;

    cudaFuncSetAttribute(mega, cudaFuncAttributeMaxDynamicSharedMemorySize, SMEM_B);

    __half *xh, *qkvh, *woh;
    float* rsum;
    int* cnt;
    cudaGetSymbolAddress((void**)&xh, g_xh);
    cudaGetSymbolAddress((void**)&qkvh, g_wqkvth);
    cudaGetSymbolAddress((void**)&woh, g_woth);
    cudaGetSymbolAddress((void**)&rsum, g_rsum);
    cudaGetSymbolAddress((void**)&cnt, g_cnt);

    // 1) x -> fp16 (+ rsum / counter zeroing)
    split_x<<<(unsigned)((RXD / 4 + 255) / 256), 256>>>(x, xh, rsum, cnt, RXD / 4);

    // 2) weights: transpose to fp16 (Wq|Wk|Wv concat, Wo separate)
    transpose_qkvo<<<dim3(DIM / 32, DIM / 32, 4), dim3(32, 8)>>>(
        Wq, Wk, Wv, Wo, qkvh, woh);

    // 3) everything else: one dependency-driven megakernel
    mega<<<N_ALL, GT, SMEM_B>>>(out);
}